// round 13
// baseline (speedup 1.0000x reference)
#include <cuda_runtime.h>
#include <cuda_fp16.h>
#include <cstdint>

// ============================================================================
// SpatialGather: out[k,c] = sum_n softmax_k(L[:,n])[k] * F[c,n] / max(S[k],1e-6)
// C=512, K=150, N=H*W=262144.
//
// Legacy mma.sync m16n8k16 FP16 path (tcgen05 unavailable at compute_103).
// v6: 2 CTAs/SM (CT=128, NR=74, grid 296, launch_bounds(256,2)) so one CTA's
// barrier/LDS phases overlap the sibling's MMA phases. 3-stage cp.async,
// ONE __syncthreads per iteration, ks order staggered by warp parity.
//
// kz (zero) -> ka (softmax -> fp16 P scratch, S sums) ->
// kb (FP16 HMMA GEMM, red.global into G) -> kc (divide).
// ============================================================================

#define KCLS 150
#define CDIM 512
#define MPAD 160              // class rows padded to 160
#define CT   128              // channels per CTA (4 c-groups)
#define NR   74               // n-ranges; grid = 4*74 = 296 = 2 CTAs/SM
#define KC   32               // pixels per chunk
#define NSTG 3                // cp.async stages
#define NTHR 256
#define PROWB 80              // P smem row stride bytes (64B data + 16 pad)
#define FROWB 160             // F smem row stride bytes (128B data + 32 pad)
#define PBYTES (MPAD * PROWB)          // 12800
#define FOFF   PBYTES                  // F tile offset in stage
#define STGB  (PBYTES + CT * FROWB)    // 33280 per stage
#define NMAX 262144

__device__ __half g_Ph[(size_t)KCLS * NMAX];  // softmax probs, fp16
__device__ float  g_G[KCLS * CDIM];           // unnormalized context accum
__device__ float  g_S[KCLS];                  // per-class prob sums

// ---------------------------------------------------------------- helpers ---
static __device__ __forceinline__ uint32_t s2u(const void* p) {
    uint32_t a;
    asm("{ .reg .u64 t; cvta.to.shared.u64 t, %1; cvt.u32.u64 %0, t; }"
        : "=r"(a) : "l"(p));
    return a;
}
static __device__ __forceinline__ void cpa16(uint32_t dst, const void* src) {
    asm volatile("cp.async.cg.shared.global [%0], [%1], 16;" :: "r"(dst), "l"(src));
}
static __device__ __forceinline__ uint32_t packh2(float lo, float hi) {
    uint32_t d;   // first PTX source -> high half
    asm("cvt.rn.f16x2.f32 %0, %1, %2;" : "=r"(d) : "f"(hi), "f"(lo));
    return d;
}

#define LDSM4(r0, r1, r2, r3, addr)                                           \
    asm volatile("ldmatrix.sync.aligned.m8n8.x4.shared.b16 {%0,%1,%2,%3}, [%4];" \
                 : "=r"(r0), "=r"(r1), "=r"(r2), "=r"(r3) : "r"(addr))

#define MMA_F16(d, a0, a1, a2, a3, b0, b1)                                    \
    asm volatile(                                                             \
        "mma.sync.aligned.m16n8k16.row.col.f32.f16.f16.f32 "                  \
        "{%0,%1,%2,%3}, {%4,%5,%6,%7}, {%8,%9}, {%0,%1,%2,%3};"               \
        : "+f"((d)[0]), "+f"((d)[1]), "+f"((d)[2]), "+f"((d)[3])              \
        : "r"(a0), "r"(a1), "r"(a2), "r"(a3), "r"(b0), "r"(b1))

static __device__ __forceinline__ void red2(float* p, float x, float y) {
    asm volatile("red.global.add.v2.f32 [%0], {%1,%2};"
                 :: "l"(p), "f"(x), "f"(y) : "memory");
}

// ---------------------------------------------------------------- kernels ---

__global__ void sg_kz() {
    int i = blockIdx.x * 256 + threadIdx.x;
    if (i < KCLS * CDIM) g_G[i] = 0.f;
    if (i < KCLS)        g_S[i] = 0.f;
}

// ka: per-pixel softmax over 150 classes (proven build, unchanged).
__global__ __launch_bounds__(256) void sg_ka(const float* __restrict__ L, int N) {
    extern __shared__ float sA[];           // [150*256] + [256] recip-sums
    float* sw = sA + KCLS * 256;
    int tid = threadIdx.x;
    size_t n0 = (size_t)blockIdx.x * 256;

    for (int idx = tid; idx < KCLS * 64; idx += 256) {
        int k = idx >> 6, j = idx & 63;
        *(float4*)(sA + k * 256 + j * 4) =
            *(const float4*)(L + (size_t)k * N + n0 + (size_t)j * 4);
    }
    __syncthreads();

    float m = -1e30f;
    #pragma unroll 5
    for (int k = 0; k < KCLS; k++) m = fmaxf(m, sA[k * 256 + tid]);
    float s = 0.f;
    #pragma unroll 5
    for (int k = 0; k < KCLS; k++) {
        float e = __expf(sA[k * 256 + tid] - m);
        sA[k * 256 + tid] = e;
        s += e;
    }
    sw[tid] = 1.0f / s;
    __syncthreads();

    for (int idx = tid; idx < KCLS * 64; idx += 256) {
        int k = idx >> 6, j = idx & 63;
        float4 e = *(float4*)(sA + k * 256 + j * 4);
        __half2 h0 = __floats2half2_rn(e.x * sw[j * 4 + 0], e.y * sw[j * 4 + 1]);
        __half2 h1 = __floats2half2_rn(e.z * sw[j * 4 + 2], e.w * sw[j * 4 + 3]);
        __half2* dst = (__half2*)(g_Ph + (size_t)k * N + n0 + (size_t)j * 4);
        dst[0] = h0;
        dst[1] = h1;
    }

    int wid = tid >> 5, lane = tid & 31;
    for (int k = wid; k < KCLS; k += 8) {
        float acc = 0.f;
        #pragma unroll
        for (int j = lane; j < 256; j += 32) acc += sA[k * 256 + j] * sw[j];
        #pragma unroll
        for (int o = 16; o; o >>= 1) acc += __shfl_xor_sync(0xffffffffu, acc, o);
        if (lane == 0) atomicAdd(&g_S[k], acc);
    }
}

// kb: G[k,c] += P(160 x n) . F(128 x n)^T via mma.sync m16n8k16 fp16.
// 8 warps, 2(m) x 4(n): warp tile 80 classes x 32 channels. 2 CTAs/SM.
// A = P fp16 via ldmatrix (80B row stride); B = F fp32 via LDS.64 + cvt
// (160B row stride). One __syncthreads per iteration; ks order staggered.
__global__ __launch_bounds__(NTHR, 2) void sg_kb(const float* __restrict__ Fp, int N) {
    extern __shared__ char smc[];
    uint32_t sb = s2u(smc);

    int tid = threadIdx.x, lane = tid & 31, w = tid >> 5;
    int g8 = lane >> 2, tg = lane & 3;
    int wm = (w >> 2) * 80;                  // warp m-offset (0 / 80)
    int wn = (w & 3) * 32;                   // warp n-offset (0..96)
    int wpar = w & 1;                        // ks stagger parity

    int r = blockIdx.x % NR;
    int cbase = (blockIdx.x / NR) * CT;

    int tc  = N / KC;                        // 8192 chunks
    int per = tc / NR, rem = tc % NR;
    int start = r * per + (r < rem ? r : rem);
    int cnt   = per + (r < rem ? 1 : 0);     // 110/111 (>= NSTG)

    // zero P pad rows (150..159, data bytes 0..63) once in every stage
    for (int i = tid; i < NSTG * 10 * 16; i += NTHR) {
        int s = i / 160, q = i % 160;
        *(float*)(smc + s * STGB + (KCLS + q / 16) * PROWB + (q % 16) * 4) = 0.f;
    }
    __syncthreads();

    float acc[5][4][4];
    #pragma unroll
    for (int a = 0; a < 5; a++)
        #pragma unroll
        for (int b = 0; b < 4; b++)
            #pragma unroll
            for (int q = 0; q < 4; q++) acc[a][b][q] = 0.f;

    auto load_stage = [&](int buf, int ch) {
        size_t px = (size_t)ch * KC;
        uint32_t base = sb + buf * STGB;
        #pragma unroll
        for (int j = 0; j < 3; j++) {        // P: 150 rows x 4 x 16B (fp16)
            int idx = j * NTHR + tid;
            if (idx < KCLS * 4) {
                int row = idx >> 2, c16 = idx & 3;
                cpa16(base + (uint32_t)(row * PROWB + c16 * 16),
                      g_Ph + (size_t)row * N + px + (size_t)c16 * 8);
            }
        }
        #pragma unroll
        for (int j = 0; j < 4; j++) {        // F: 128 rows x 8 x 16B (fp32)
            int idx = j * NTHR + tid;
            int row = idx >> 3, c16 = idx & 7;
            cpa16(base + FOFF + (uint32_t)(row * FROWB + c16 * 16),
                  Fp + (size_t)(cbase + row) * N + px + (size_t)c16 * 4);
        }
        asm volatile("cp.async.commit_group;" ::: "memory");
    };

    // prologue: NSTG-1 stages in flight
    #pragma unroll
    for (int s = 0; s < NSTG - 1; s++) load_stage(s, start + s);

    // per-thread ldmatrix row/col selector (constant across chunks)
    int arow = (lane & 7) + ((lane & 8) ? 8 : 0);
    uint32_t acol = (lane & 16) ? 16u : 0u;

    for (int i = 0; i < cnt; ++i) {
        int st = i % NSTG;
        asm volatile("cp.async.wait_group %0;" :: "n"(NSTG - 2));
        __syncthreads();   // stage i ready for all; stage (i-1) free for all

        uint32_t pbase = sb + st * STGB;
        const float* fS = (const float*)(smc + st * STGB + FOFF);

        #pragma unroll
        for (int s = 0; s < 2; s++) {        // two k16 steps, order by parity
            int ks = s ^ wpar;
            uint32_t b0[4], b1[4];
            #pragma unroll
            for (int nt = 0; nt < 4; nt++) {
                const float* fp = fS + (wn + nt * 8 + g8) * (FROWB / 4)
                                + ks * 16 + tg * 2;
                float2 lo = *(const float2*)fp;        // k, k+1
                float2 hi = *(const float2*)(fp + 8);  // k+8, k+9
                b0[nt] = packh2(lo.x, lo.y);
                b1[nt] = packh2(hi.x, hi.y);
            }
            #pragma unroll
            for (int mt = 0; mt < 5; mt++) {
                uint32_t addr = pbase + (uint32_t)(wm + mt * 16 + arow) * PROWB
                              + acol + ks * 32;
                uint32_t a0, a1, a2, a3;
                LDSM4(a0, a1, a2, a3, addr);
                #pragma unroll
                for (int nt = 0; nt < 4; nt++)
                    MMA_F16(acc[mt][nt], a0, a1, a2, a3, b0[nt], b1[nt]);
            }
        }

        // refill the stage consumed at iter i-1 (ordered by the sync above)
        if (i + NSTG - 1 < cnt) load_stage((i + NSTG - 1) % NSTG, start + i + NSTG - 1);
        else asm volatile("cp.async.commit_group;" ::: "memory");  // keep count
    }

    // ---- epilogue: partial sums -> G via vector red ----
    #pragma unroll
    for (int mt = 0; mt < 5; mt++) {
        #pragma unroll
        for (int nt = 0; nt < 4; nt++) {
            int m0 = wm + mt * 16 + g8;
            int c  = cbase + wn + nt * 8 + 2 * tg;
            if (m0 < KCLS)     red2(&g_G[m0 * CDIM + c], acc[mt][nt][0], acc[mt][nt][1]);
            if (m0 + 8 < KCLS) red2(&g_G[(m0 + 8) * CDIM + c], acc[mt][nt][2], acc[mt][nt][3]);
        }
    }
}

// kc: final column normalization
__global__ void sg_kc(float* __restrict__ out) {
    int i = blockIdx.x * 256 + threadIdx.x;
    if (i < KCLS * CDIM) {
        int k = i >> 9;
        out[i] = g_G[i] / fmaxf(g_S[k], 1e-6f);
    }
}

// ---------------------------------------------------------------- launch ----

#define SMEM_A ((KCLS * 256 + 256) * 4)      // 154624 bytes
#define SMEM_B (NSTG * STGB)                 // 99840 bytes (2 CTAs/SM)

extern "C" void kernel_launch(void* const* d_in, const int* in_sizes, int n_in,
                              void* d_out, int out_size) {
    const float* F = (const float*)d_in[0];   // feats_chw  (512, H, W)
    const float* L = (const float*)d_in[1];   // class_logits_chw (150, H, W)
    float* out = (float*)d_out;               // (150, 512) fp32
    int N = in_sizes[1] / KCLS;               // H*W

    cudaFuncSetAttribute(sg_ka, cudaFuncAttributeMaxDynamicSharedMemorySize, SMEM_A);
    cudaFuncSetAttribute(sg_kb, cudaFuncAttributeMaxDynamicSharedMemorySize, SMEM_B);

    sg_kz<<<(KCLS * CDIM + 255) / 256, 256>>>();
    sg_ka<<<N / 256, 256, SMEM_A>>>(L, N);
    sg_kb<<<4 * NR, NTHR, SMEM_B>>>(F, N);
    sg_kc<<<(KCLS * CDIM + 255) / 256, 256>>>(out);
}

// round 14
// speedup vs baseline: 1.2320x; 1.2320x over previous
#include <cuda_runtime.h>
#include <cuda_fp16.h>
#include <cstdint>

// ============================================================================
// SpatialGather: out[k,c] = sum_n softmax_k(L[:,n])[k] * F[c,n] / max(S[k],1e-6)
// C=512, K=150, N=H*W=262144.
//
// Legacy mma.sync m16n8k16 FP16 path (tcgen05 unavailable at compute_103).
// v7 FUSED: softmax computed in-kernel on the staged L tile; fp16 P written
// to smem (overlaying L) in the MMA layout. No P scratch in global, no ka.
// 3-stage cp.async, 512 threads, CT=256, NR=74, grid 148.
//
// kz (zero accums) -> kf (fused softmax + FP16 HMMA GEMM + S sums) ->
// kc (divide).
// ============================================================================

#define KCLS 150
#define CDIM 512
#define CT   256              // channels per CTA (2 c-groups)
#define NR   74               // n-ranges; grid = 2*74 = 148 CTAs
#define KC   32               // pixels per chunk
#define NSTG 3                // cp.async stages
#define NTHR 512
#define LROWB 144             // L smem row stride bytes (128B data + 16 pad)
#define PROWB 80              // P overlay row stride bytes (64B data + 16 pad)
#define FROWB 160             // F smem row stride bytes (128B data + 32 pad)
#define LPBYTES 23040         // L/P region: 160 rows x 144B
#define FOFF  LPBYTES         // F tile offset in stage
#define STGB  (LPBYTES + CT * FROWB)   // 64000 per stage

__device__ float g_G[KCLS * CDIM];    // unnormalized context accumulator
__device__ float g_S[KCLS];           // per-class prob sums

// ---------------------------------------------------------------- helpers ---
static __device__ __forceinline__ uint32_t s2u(const void* p) {
    uint32_t a;
    asm("{ .reg .u64 t; cvta.to.shared.u64 t, %1; cvt.u32.u64 %0, t; }"
        : "=r"(a) : "l"(p));
    return a;
}
static __device__ __forceinline__ void cpa16(uint32_t dst, const void* src) {
    asm volatile("cp.async.cg.shared.global [%0], [%1], 16;" :: "r"(dst), "l"(src));
}
static __device__ __forceinline__ uint32_t packh2(float lo, float hi) {
    uint32_t d;   // first PTX source -> high half
    asm("cvt.rn.f16x2.f32 %0, %1, %2;" : "=r"(d) : "f"(hi), "f"(lo));
    return d;
}
static __device__ __forceinline__ float h2sum(uint32_t u) {
    __half2 h = *reinterpret_cast<__half2*>(&u);
    float2 f = __half22float2(h);
    return f.x + f.y;
}

#define LDSM4(r0, r1, r2, r3, addr)                                           \
    asm volatile("ldmatrix.sync.aligned.m8n8.x4.shared.b16 {%0,%1,%2,%3}, [%4];" \
                 : "=r"(r0), "=r"(r1), "=r"(r2), "=r"(r3) : "r"(addr))

#define MMA_F16(d, a0, a1, a2, a3, b0, b1)                                    \
    asm volatile(                                                             \
        "mma.sync.aligned.m16n8k16.row.col.f32.f16.f16.f32 "                  \
        "{%0,%1,%2,%3}, {%4,%5,%6,%7}, {%8,%9}, {%0,%1,%2,%3};"               \
        : "+f"((d)[0]), "+f"((d)[1]), "+f"((d)[2]), "+f"((d)[3])              \
        : "r"(a0), "r"(a1), "r"(a2), "r"(a3), "r"(b0), "r"(b1))

static __device__ __forceinline__ void red1(float* p, float x) {
    asm volatile("red.global.add.f32 [%0], %1;" :: "l"(p), "f"(x) : "memory");
}
static __device__ __forceinline__ void red2(float* p, float x, float y) {
    asm volatile("red.global.add.v2.f32 [%0], {%1,%2};"
                 :: "l"(p), "f"(x), "f"(y) : "memory");
}

// ---------------------------------------------------------------- kernels ---

__global__ void sg_kz() {
    int i = blockIdx.x * 256 + threadIdx.x;
    if (i < KCLS * CDIM) g_G[i] = 0.f;
    if (i < KCLS)        g_S[i] = 0.f;
}

// kf: fused per-pixel softmax + GEMM.
// Per 32-px chunk: stage L(150x32 fp32, 144B rows) + F(256x128B, 160B rows);
// softmax in regs (half-warp owns a pixel), fp16 P overlaid on L region
// (80B rows = R12 MMA layout); ldmatrix+mma.sync identical to R12;
// S[k] summed from the P tile (threads<150), red.global at end (c-group 0).
__global__ __launch_bounds__(NTHR, 1) void sg_kf(const float* __restrict__ Fp,
                                                 const float* __restrict__ Lp,
                                                 int N) {
    extern __shared__ char smc[];
    uint32_t sb = s2u(smc);

    int tid = threadIdx.x, lane = tid & 31, w = tid >> 5;
    int g8 = lane >> 2, tg = lane & 3;
    int wm = (w >> 3) * 80;                  // warp m-offset (0 / 80)
    int wn = (w & 7) * 32;                   // warp n-offset (0..224)
    int px = (w << 1) | (lane >> 4);         // this half-warp's pixel (0..31)
    int l16 = lane & 15;

    int r = blockIdx.x >> 1;                 // n-range (adjacent bids pair up
    int cbase = (blockIdx.x & 1) * CT;       //  on adjacent SMs -> L2 share L)

    int tc  = N / KC;                        // 8192 chunks
    int per = tc / NR, rem = tc % NR;
    int start = r * per + (r < rem ? r : rem);
    int cnt   = per + (r < rem ? 1 : 0);     // 110/111 (>= NSTG)

    float acc[5][4][4];
    #pragma unroll
    for (int a = 0; a < 5; a++)
        #pragma unroll
        for (int b = 0; b < 4; b++)
            #pragma unroll
            for (int q = 0; q < 4; q++) acc[a][b][q] = 0.f;
    float sS = 0.f;                          // per-thread S row accumulator

    auto load_stage = [&](int buf, int ch) {
        size_t pxg = (size_t)ch * KC;
        uint32_t base = sb + buf * STGB;
        #pragma unroll
        for (int j = 0; j < 3; j++) {        // L: 150 rows x 8 x 16B (fp32)
            int idx = j * NTHR + tid;
            if (idx < KCLS * 8) {
                int row = idx >> 3, c16 = idx & 7;
                cpa16(base + (uint32_t)(row * LROWB + c16 * 16),
                      Lp + (size_t)row * N + pxg + (size_t)c16 * 4);
            }
        }
        #pragma unroll
        for (int j = 0; j < 4; j++) {        // F: 256 rows x 8 x 16B (fp32)
            int idx = j * NTHR + tid;
            int row = idx >> 3, c16 = idx & 7;
            cpa16(base + FOFF + (uint32_t)(row * FROWB + c16 * 16),
                  Fp + (size_t)(cbase + row) * N + pxg + (size_t)c16 * 4);
        }
        asm volatile("cp.async.commit_group;" ::: "memory");
    };

    #pragma unroll
    for (int s = 0; s < NSTG - 1; s++) load_stage(s, start + s);

    // per-thread ldmatrix row/col selector (constant across chunks)
    int arow = (lane & 7) + ((lane & 8) ? 8 : 0);
    uint32_t acol = (lane & 16) ? 16u : 0u;

    for (int i = 0; i < cnt; ++i) {
        int st = i % NSTG;
        asm volatile("cp.async.wait_group %0;" :: "n"(NSTG - 2));
        __syncthreads();                      // stage i loaded; stage i-1 free

        char* base = smc + st * STGB;
        uint32_t ubase = sb + st * STGB;

        // ---- softmax for this half-warp's pixel (rows l16+16j) ----
        float lv[10];
        float m = -1e30f;
        #pragma unroll
        for (int j = 0; j < 10; j++) {
            int kr = l16 + 16 * j;
            if (kr < KCLS) {
                lv[j] = *(const float*)(base + kr * LROWB + px * 4);
                m = fmaxf(m, lv[j]);
            }
        }
        #pragma unroll
        for (int o = 8; o; o >>= 1) m = fmaxf(m, __shfl_xor_sync(0xffffffffu, m, o));
        float s = 0.f;
        #pragma unroll
        for (int j = 0; j < 10; j++) {
            int kr = l16 + 16 * j;
            if (kr < KCLS) { lv[j] = __expf(lv[j] - m); s += lv[j]; }
        }
        #pragma unroll
        for (int o = 8; o; o >>= 1) s += __shfl_xor_sync(0xffffffffu, s, o);
        float rs = 1.0f / s;

        __syncthreads();                      // all L reads done before overlay

        // ---- write fp16 P overlay (80B rows) + zero pad rows 150..159 ----
        #pragma unroll
        for (int j = 0; j < 10; j++) {
            int kr = l16 + 16 * j;
            if (kr < KCLS)
                *(__half*)(base + kr * PROWB + px * 2) = __float2half_rn(lv[j] * rs);
        }
        if (tid < 200) *(uint32_t*)(base + KCLS * PROWB + tid * 4) = 0u;

        __syncthreads();                      // P visible to all

        // ---- MMA phase (identical to proven R12) ----
        const float* fS = (const float*)(base + FOFF);
        #pragma unroll
        for (int ks = 0; ks < 2; ks++) {
            uint32_t b0[4], b1[4];
            #pragma unroll
            for (int nt = 0; nt < 4; nt++) {
                const float* fp = fS + (wn + nt * 8 + g8) * (FROWB / 4)
                                + ks * 16 + tg * 2;
                float2 lo = *(const float2*)fp;
                float2 hi = *(const float2*)(fp + 8);
                b0[nt] = packh2(lo.x, lo.y);
                b1[nt] = packh2(hi.x, hi.y);
            }
            #pragma unroll
            for (int mt = 0; mt < 5; mt++) {
                uint32_t addr = ubase + (uint32_t)(wm + mt * 16 + arow) * PROWB
                              + acol + ks * 32;
                uint32_t a0, a1, a2, a3;
                LDSM4(a0, a1, a2, a3, addr);
                #pragma unroll
                for (int nt = 0; nt < 4; nt++)
                    MMA_F16(acc[mt][nt], a0, a1, a2, a3, b0[nt], b1[nt]);
            }
        }

        // ---- S row sums from the P tile (c-group 0 only) ----
        if (cbase == 0 && tid < KCLS) {
            const uint4* prow = (const uint4*)(base + tid * PROWB);
            float rsum = 0.f;
            #pragma unroll
            for (int q = 0; q < 4; q++) {
                uint4 v = prow[q];
                rsum += h2sum(v.x) + h2sum(v.y) + h2sum(v.z) + h2sum(v.w);
            }
            sS += rsum;
        }

        // refill the stage consumed at iter i-1 (ordered by top sync)
        if (i + NSTG - 1 < cnt) load_stage((i + NSTG - 1) % NSTG, start + i + NSTG - 1);
        else asm volatile("cp.async.commit_group;" ::: "memory");  // keep count
    }

    // ---- epilogue ----
    if (cbase == 0 && tid < KCLS) red1(&g_S[tid], sS);

    #pragma unroll
    for (int mt = 0; mt < 5; mt++) {
        #pragma unroll
        for (int nt = 0; nt < 4; nt++) {
            int m0 = wm + mt * 16 + g8;
            int c  = cbase + wn + nt * 8 + 2 * tg;
            if (m0 < KCLS)     red2(&g_G[m0 * CDIM + c], acc[mt][nt][0], acc[mt][nt][1]);
            if (m0 + 8 < KCLS) red2(&g_G[(m0 + 8) * CDIM + c], acc[mt][nt][2], acc[mt][nt][3]);
        }
    }
}

// kc: final column normalization
__global__ void sg_kc(float* __restrict__ out) {
    int i = blockIdx.x * 256 + threadIdx.x;
    if (i < KCLS * CDIM) {
        int k = i >> 9;
        out[i] = g_G[i] / fmaxf(g_S[k], 1e-6f);
    }
}

// ---------------------------------------------------------------- launch ----

#define SMEM_F (NSTG * STGB)                 // 192000 bytes

extern "C" void kernel_launch(void* const* d_in, const int* in_sizes, int n_in,
                              void* d_out, int out_size) {
    const float* F = (const float*)d_in[0];   // feats_chw  (512, H, W)
    const float* L = (const float*)d_in[1];   // class_logits_chw (150, H, W)
    float* out = (float*)d_out;               // (150, 512) fp32
    int N = in_sizes[1] / KCLS;               // H*W

    cudaFuncSetAttribute(sg_kf, cudaFuncAttributeMaxDynamicSharedMemorySize, SMEM_F);

    sg_kz<<<(KCLS * CDIM + 255) / 256, 256>>>();
    sg_kf<<<2 * NR, NTHR, SMEM_F>>>(F, L, N);
    sg_kc<<<(KCLS * CDIM + 255) / 256, 256>>>(out);
}